// round 3
// baseline (speedup 1.0000x reference)
#include <cuda_runtime.h>

#define N_NODES 100000
#define N_EDGES 1600000
#define HIDDEN 64
#define N_LAYERS 4
#define BN_EPS 1e-5f

#define SCAN_B 512
#define SCAN_NB ((N_NODES + SCAN_B - 1) / SCAN_B)   // 196

// ---------------- scratch (no allocation allowed) ----------------
__device__ float  g_agg[(size_t)N_NODES * HIDDEN];   // holds z_in = h + agg
__device__ float  g_z  [(size_t)N_NODES * HIDDEN];
__device__ double g_sum[HIDDEN];
__device__ double g_sq [HIDDEN];
__device__ float  g_scale[HIDDEN];
__device__ float  g_shift[HIDDEN];
// CSR build
__device__ int g_count[N_NODES];
__device__ int g_scan [SCAN_NB * SCAN_B];
__device__ int g_bsumx[SCAN_NB];
__device__ int g_off  [N_NODES + 1];
__device__ int g_cursor[N_NODES];
__device__ int g_perm [N_EDGES];

// ---------------- init: h = node_feat, zero g_count ----------------
__global__ void copy_h_kernel(const float* __restrict__ src, float* __restrict__ dst) {
    int i = blockIdx.x * blockDim.x + threadIdx.x;
    if (i < N_NODES * HIDDEN / 4)
        ((float4*)dst)[i] = ((const float4*)src)[i];
    if (i < N_NODES) g_count[i] = 0;
}

// ---------------- CSR build ----------------
__global__ void csr_hist_kernel(const int* __restrict__ dst) {
    int e = blockIdx.x * blockDim.x + threadIdx.x;
    if (e < N_EDGES) atomicAdd(&g_count[dst[e]], 1);
}

__global__ __launch_bounds__(SCAN_B) void csr_scan1_kernel() {
    __shared__ int s[SCAN_B];
    int t = threadIdx.x;
    int idx = blockIdx.x * SCAN_B + t;
    int v = (idx < N_NODES) ? g_count[idx] : 0;
    s[t] = v;
    __syncthreads();
    #pragma unroll
    for (int off = 1; off < SCAN_B; off <<= 1) {
        int x = (t >= off) ? s[t - off] : 0;
        __syncthreads();
        s[t] += x;
        __syncthreads();
    }
    g_scan[idx] = s[t];
    if (t == SCAN_B - 1) g_bsumx[blockIdx.x] = s[t];
}

__global__ __launch_bounds__(256) void csr_scan2_kernel() {
    __shared__ int s[256];
    int t = threadIdx.x;
    s[t] = (t < SCAN_NB) ? g_bsumx[t] : 0;
    __syncthreads();
    #pragma unroll
    for (int off = 1; off < 256; off <<= 1) {
        int x = (t >= off) ? s[t - off] : 0;
        __syncthreads();
        s[t] += x;
        __syncthreads();
    }
    if (t < SCAN_NB) g_bsumx[t] = s[t];   // inclusive block sums
}

__global__ __launch_bounds__(SCAN_B) void csr_scan3_kernel() {
    int t = threadIdx.x;
    int b = blockIdx.x;
    int idx = b * SCAN_B + t;
    if (idx < N_NODES) {
        int base = (b > 0) ? g_bsumx[b - 1] : 0;
        int excl = g_scan[idx] - g_count[idx] + base;   // exclusive prefix
        g_off[idx] = excl;
        g_cursor[idx] = excl;
    }
    if (idx == 0) g_off[N_NODES] = N_EDGES;
}

__global__ void csr_place_kernel(const int* __restrict__ dst) {
    int e = blockIdx.x * blockDim.x + threadIdx.x;
    if (e < N_EDGES) {
        int pos = atomicAdd(&g_cursor[dst[e]], 1);
        g_perm[pos] = e;
    }
}

// ---------------- pull gather: g_agg[n] = h[n] + sum_{e: dst==n} relu(h[src]+ef@We+be) ----------------
// One warp per node. Lanes 0-15 handle even edges of the segment, 16-31 odd.
__global__ __launch_bounds__(256) void gather_kernel(
    const float* __restrict__ h,
    const float* __restrict__ ef,
    const int*   __restrict__ src,
    const float* __restrict__ We,
    const float* __restrict__ be)
{
    __shared__ float sWe[4 * HIDDEN];
    __shared__ float sbe[HIDDEN];
    int tid = threadIdx.x;
    for (int i = tid; i < 4 * HIDDEN; i += blockDim.x) sWe[i] = We[i];
    if (tid < HIDDEN) sbe[tid] = be[tid];
    if (blockIdx.x == 0 && tid < HIDDEN) { g_sum[tid] = 0.0; g_sq[tid] = 0.0; }
    __syncthreads();

    const int n    = blockIdx.x * 8 + (tid >> 5);   // node id (grid covers exactly N)
    const int lane = tid & 31;
    const int half = lane >> 4;
    const int fl   = lane & 15;
    const int f0   = fl * 4;

    const int beg = g_off[n];
    const int end = g_off[n + 1];

    float4 acc = make_float4(0.f, 0.f, 0.f, 0.f);
    for (int i = beg + half; i < end; i += 2) {
        int e = __ldg(g_perm + i);
        int s = __ldg(src + e);
        float4 efv = __ldg(((const float4*)ef) + e);
        float m0 = sbe[f0 + 0] + efv.x * sWe[0 * HIDDEN + f0 + 0] + efv.y * sWe[1 * HIDDEN + f0 + 0]
                               + efv.z * sWe[2 * HIDDEN + f0 + 0] + efv.w * sWe[3 * HIDDEN + f0 + 0];
        float m1 = sbe[f0 + 1] + efv.x * sWe[0 * HIDDEN + f0 + 1] + efv.y * sWe[1 * HIDDEN + f0 + 1]
                               + efv.z * sWe[2 * HIDDEN + f0 + 1] + efv.w * sWe[3 * HIDDEN + f0 + 1];
        float m2 = sbe[f0 + 2] + efv.x * sWe[0 * HIDDEN + f0 + 2] + efv.y * sWe[1 * HIDDEN + f0 + 2]
                               + efv.z * sWe[2 * HIDDEN + f0 + 2] + efv.w * sWe[3 * HIDDEN + f0 + 2];
        float m3 = sbe[f0 + 3] + efv.x * sWe[0 * HIDDEN + f0 + 3] + efv.y * sWe[1 * HIDDEN + f0 + 3]
                               + efv.z * sWe[2 * HIDDEN + f0 + 3] + efv.w * sWe[3 * HIDDEN + f0 + 3];
        float4 hv = __ldg(((const float4*)(h + (size_t)s * HIDDEN)) + fl);
        acc.x += fmaxf(m0 + hv.x, 0.f);
        acc.y += fmaxf(m1 + hv.y, 0.f);
        acc.z += fmaxf(m2 + hv.z, 0.f);
        acc.w += fmaxf(m3 + hv.w, 0.f);
    }
    // combine the two halves
    acc.x += __shfl_xor_sync(0xFFFFFFFFu, acc.x, 16);
    acc.y += __shfl_xor_sync(0xFFFFFFFFu, acc.y, 16);
    acc.z += __shfl_xor_sync(0xFFFFFFFFu, acc.z, 16);
    acc.w += __shfl_xor_sync(0xFFFFFFFFu, acc.w, 16);

    if (half == 0) {
        float4 hv = __ldg(((const float4*)(h + (size_t)n * HIDDEN)) + fl);
        acc.x += hv.x; acc.y += hv.y; acc.z += hv.z; acc.w += hv.w;
        *(((float4*)(g_agg + (size_t)n * HIDDEN)) + fl) = acc;
    }
}

// ---------------- MLP: z = relu(z_in@W1+b1)@W2+b2, plus per-feature stats ----------------
// 256 threads, 64 nodes/block. Each thread: 4 nodes x 4 features. Dynamic smem.
__global__ __launch_bounds__(256) void mlp_kernel(
    const float* __restrict__ W1, const float* __restrict__ b1,
    const float* __restrict__ W2, const float* __restrict__ b2)
{
    extern __shared__ float smem[];
    float* sW = smem;                                   // 64*64
    float (*sIn)[HIDDEN + 1] = (float(*)[HIDDEN + 1])(smem + HIDDEN * HIDDEN);
    float (*sT )[HIDDEN + 1] = (float(*)[HIDDEN + 1])(smem + HIDDEN * HIDDEN + 64 * (HIDDEN + 1));

    const int tid = threadIdx.x;
    const int tf = tid & 15;
    const int tn = tid >> 4;     // 0..15
    const int f0 = tf * 4;
    const int n0 = tn * 4;
    const int node0 = blockIdx.x * 64;

    for (int i = tid; i < HIDDEN * HIDDEN; i += 256) sW[i] = __ldg(W1 + i);
    for (int i = tid; i < 64 * HIDDEN / 4; i += 256) {
        int nn = i >> 4, c = i & 15;
        float4 v = (node0 + nn < N_NODES)
                 ? *(((const float4*)(g_agg + (size_t)(node0 + nn) * HIDDEN)) + c)
                 : make_float4(0.f, 0.f, 0.f, 0.f);
        sIn[nn][c * 4 + 0] = v.x; sIn[nn][c * 4 + 1] = v.y;
        sIn[nn][c * 4 + 2] = v.z; sIn[nn][c * 4 + 3] = v.w;
    }
    __syncthreads();

    float acc[4][4];
    {
        float4 bias = __ldg(((const float4*)b1) + tf);
        #pragma unroll
        for (int i = 0; i < 4; i++) {
            acc[i][0] = bias.x; acc[i][1] = bias.y; acc[i][2] = bias.z; acc[i][3] = bias.w;
        }
    }
    #pragma unroll 4
    for (int k = 0; k < HIDDEN; k++) {
        float4 w = *(const float4*)(sW + k * HIDDEN + f0);
        #pragma unroll
        for (int i = 0; i < 4; i++) {
            float a = sIn[n0 + i][k];
            acc[i][0] += a * w.x; acc[i][1] += a * w.y;
            acc[i][2] += a * w.z; acc[i][3] += a * w.w;
        }
    }
    #pragma unroll
    for (int i = 0; i < 4; i++)
        #pragma unroll
        for (int j = 0; j < 4; j++)
            sT[n0 + i][f0 + j] = fmaxf(acc[i][j], 0.f);
    __syncthreads();

    for (int i = tid; i < HIDDEN * HIDDEN; i += 256) sW[i] = __ldg(W2 + i);
    __syncthreads();

    {
        float4 bias = __ldg(((const float4*)b2) + tf);
        #pragma unroll
        for (int i = 0; i < 4; i++) {
            acc[i][0] = bias.x; acc[i][1] = bias.y; acc[i][2] = bias.z; acc[i][3] = bias.w;
        }
    }
    #pragma unroll 4
    for (int k = 0; k < HIDDEN; k++) {
        float4 w = *(const float4*)(sW + k * HIDDEN + f0);
        #pragma unroll
        for (int i = 0; i < 4; i++) {
            float a = sT[n0 + i][k];
            acc[i][0] += a * w.x; acc[i][1] += a * w.y;
            acc[i][2] += a * w.z; acc[i][3] += a * w.w;
        }
    }

    // write z + per-thread stats partials (guard tail block)
    float ps[4], pq[4];
    #pragma unroll
    for (int j = 0; j < 4; j++) { ps[j] = 0.f; pq[j] = 0.f; }
    #pragma unroll
    for (int i = 0; i < 4; i++) {
        int node = node0 + n0 + i;
        if (node < N_NODES) {
            float4 v = make_float4(acc[i][0], acc[i][1], acc[i][2], acc[i][3]);
            *(((float4*)(g_z + (size_t)node * HIDDEN)) + tf) = v;
            #pragma unroll
            for (int j = 0; j < 4; j++) { ps[j] += acc[i][j]; pq[j] += acc[i][j] * acc[i][j]; }
        }
    }

    // block reduce over 16 node-groups (reuse sIn as scratch: 16*64 sums + 16*64 sqs)
    __syncthreads();
    float* rs = &sIn[0][0];            // 1024 floats
    float* rq = &sIn[0][0] + 1024;     // 1024 floats
    #pragma unroll
    for (int j = 0; j < 4; j++) {
        rs[tn * HIDDEN + f0 + j] = ps[j];
        rq[tn * HIDDEN + f0 + j] = pq[j];
    }
    __syncthreads();
    if (tid < HIDDEN) {
        float s = 0.f, q = 0.f;
        #pragma unroll
        for (int g = 0; g < 16; g++) {
            s += rs[g * HIDDEN + tid];
            q += rq[g * HIDDEN + tid];
        }
        atomicAdd(&g_sum[tid], (double)s);
        atomicAdd(&g_sq[tid],  (double)q);
    }
}

// ---------------- BN prep ----------------
__global__ void bnprep_kernel(const float* __restrict__ gamma, const float* __restrict__ beta) {
    int f = threadIdx.x;
    if (f < HIDDEN) {
        double inv_n = 1.0 / (double)N_NODES;
        double mu  = g_sum[f] * inv_n;
        double var = g_sq[f] * inv_n - mu * mu;
        float rstd = rsqrtf((float)var + BN_EPS);
        float g = gamma[f];
        g_scale[f] = g * rstd;
        g_shift[f] = beta[f] - g * rstd * (float)mu;
    }
}

// ---------------- BN + ReLU + residual: h = relu(scale*z + shift) + h ----------------
__global__ __launch_bounds__(256) void bn_kernel(float* __restrict__ h) {
    int i = blockIdx.x * blockDim.x + threadIdx.x;
    if (i >= N_NODES * HIDDEN / 4) return;
    int c = i & 15;
    float4 z  = ((const float4*)g_z)[i];
    float4 hv = ((float4*)h)[i];
    float4 sc = *(((const float4*)g_scale) + c);
    float4 sh = *(((const float4*)g_shift) + c);
    hv.x += fmaxf(z.x * sc.x + sh.x, 0.f);
    hv.y += fmaxf(z.y * sc.y + sh.y, 0.f);
    hv.z += fmaxf(z.z * sc.z + sh.z, 0.f);
    hv.w += fmaxf(z.w * sc.w + sh.w, 0.f);
    ((float4*)h)[i] = hv;
}

// ---------------- launch ----------------
extern "C" void kernel_launch(void* const* d_in, const int* in_sizes, int n_in,
                              void* d_out, int out_size) {
    const float* node_feat = (const float*)d_in[0];
    const float* edge_feat = (const float*)d_in[1];
    const int*   src       = (const int*)  d_in[2];
    const int*   dst       = (const int*)  d_in[3];
    const float* We        = (const float*)d_in[4];
    const float* be        = (const float*)d_in[5];
    const float* W1        = (const float*)d_in[6];
    const float* b1        = (const float*)d_in[7];
    const float* W2        = (const float*)d_in[8];
    const float* b2        = (const float*)d_in[9];
    const float* gamma     = (const float*)d_in[10];
    const float* beta      = (const float*)d_in[11];
    float* h = (float*)d_out;

    const int MLP_SMEM = (HIDDEN * HIDDEN + 2 * 64 * (HIDDEN + 1)) * sizeof(float); // 49664
    static bool attr_set = false;
    if (!attr_set) {
        cudaFuncSetAttribute(mlp_kernel, cudaFuncAttributeMaxDynamicSharedMemorySize, MLP_SMEM);
        attr_set = true;
    }

    const int ELEM4 = N_NODES * HIDDEN / 4;      // 1.6M
    const int VEC_BLOCKS = (ELEM4 + 255) / 256;  // 6250
    const int EDGE_BLOCKS = (N_EDGES + 255) / 256;

    copy_h_kernel<<<VEC_BLOCKS, 256>>>(node_feat, h);
    csr_hist_kernel<<<EDGE_BLOCKS, 256>>>(dst);
    csr_scan1_kernel<<<SCAN_NB, SCAN_B>>>();
    csr_scan2_kernel<<<1, 256>>>();
    csr_scan3_kernel<<<SCAN_NB, SCAN_B>>>();
    csr_place_kernel<<<EDGE_BLOCKS, 256>>>(dst);

    for (int l = 0; l < N_LAYERS; l++) {
        gather_kernel<<<N_NODES / 8, 256>>>(h, edge_feat, src, We, be);
        mlp_kernel<<<(N_NODES + 63) / 64, 256, MLP_SMEM>>>(
            W1 + (size_t)l * HIDDEN * HIDDEN, b1 + (size_t)l * HIDDEN,
            W2 + (size_t)l * HIDDEN * HIDDEN, b2 + (size_t)l * HIDDEN);
        bnprep_kernel<<<1, 64>>>(gamma + (size_t)l * HIDDEN, beta + (size_t)l * HIDDEN);
        bn_kernel<<<VEC_BLOCKS, 256>>>(h);
    }
}

// round 8
// speedup vs baseline: 1.1639x; 1.1639x over previous
#include <cuda_runtime.h>

#define N_NODES 100000
#define N_EDGES 1600000
#define HIDDEN 64
#define N_LAYERS 4
#define BN_EPS 1e-5f
#define PITCH 68   // 272B rows: 16B-aligned, conflict-free broadcast

#define SCAN_B 512
#define SCAN_NB ((N_NODES + SCAN_B - 1) / SCAN_B)   // 196

// ---------------- scratch (no allocation allowed) ----------------
__device__ float  g_agg[(size_t)N_NODES * HIDDEN];   // holds z_in = h + agg
__device__ float  g_z  [(size_t)N_NODES * HIDDEN];
__device__ double g_sum[HIDDEN];
__device__ double g_sq [HIDDEN];
// CSR build
__device__ int   g_count[N_NODES];
__device__ int   g_scan [SCAN_NB * SCAN_B];
__device__ int   g_bsumx[SCAN_NB];
__device__ int   g_off  [N_NODES + 1];
__device__ int   g_cursor[N_NODES];
__device__ int   g_perm [N_EDGES];
// permuted edge data (contiguous per dst-segment)
__device__ int   g_src_s[N_EDGES];
__device__ float g_ef_s [(size_t)N_EDGES * 4];

// ---------------- init: h = node_feat, zero g_count ----------------
__global__ void copy_h_kernel(const float* __restrict__ src, float* __restrict__ dst) {
    int i = blockIdx.x * blockDim.x + threadIdx.x;
    if (i < N_NODES * HIDDEN / 4)
        ((float4*)dst)[i] = ((const float4*)src)[i];
    if (i < N_NODES) g_count[i] = 0;
}

// ---------------- CSR build ----------------
__global__ void csr_hist_kernel(const int* __restrict__ dst) {
    int e = blockIdx.x * blockDim.x + threadIdx.x;
    if (e < N_EDGES) atomicAdd(&g_count[dst[e]], 1);
}

__global__ __launch_bounds__(SCAN_B) void csr_scan1_kernel() {
    __shared__ int s[SCAN_B];
    int t = threadIdx.x;
    int idx = blockIdx.x * SCAN_B + t;
    int v = (idx < N_NODES) ? g_count[idx] : 0;
    s[t] = v;
    __syncthreads();
    #pragma unroll
    for (int off = 1; off < SCAN_B; off <<= 1) {
        int x = (t >= off) ? s[t - off] : 0;
        __syncthreads();
        s[t] += x;
        __syncthreads();
    }
    g_scan[idx] = s[t];
    if (t == SCAN_B - 1) g_bsumx[blockIdx.x] = s[t];
}

__global__ __launch_bounds__(256) void csr_scan2_kernel() {
    __shared__ int s[256];
    int t = threadIdx.x;
    s[t] = (t < SCAN_NB) ? g_bsumx[t] : 0;
    __syncthreads();
    #pragma unroll
    for (int off = 1; off < 256; off <<= 1) {
        int x = (t >= off) ? s[t - off] : 0;
        __syncthreads();
        s[t] += x;
        __syncthreads();
    }
    if (t < SCAN_NB) g_bsumx[t] = s[t];
}

__global__ __launch_bounds__(SCAN_B) void csr_scan3_kernel() {
    int t = threadIdx.x;
    int b = blockIdx.x;
    int idx = b * SCAN_B + t;
    if (idx < N_NODES) {
        int base = (b > 0) ? g_bsumx[b - 1] : 0;
        int excl = g_scan[idx] - g_count[idx] + base;
        g_off[idx] = excl;
        g_cursor[idx] = excl;
    }
    if (idx == 0) g_off[N_NODES] = N_EDGES;
}

__global__ void csr_place_kernel(const int* __restrict__ dst) {
    int e = blockIdx.x * blockDim.x + threadIdx.x;
    if (e < N_EDGES) {
        int pos = atomicAdd(&g_cursor[dst[e]], 1);
        g_perm[pos] = e;
    }
}

// ---------------- permute edge data into dst-sorted order (once, reused x4) ----------------
__global__ void permute_kernel(const int* __restrict__ src, const float* __restrict__ ef) {
    int i = blockIdx.x * blockDim.x + threadIdx.x;
    if (i < N_EDGES) {
        int e = __ldg(g_perm + i);
        g_src_s[i] = __ldg(src + e);
        ((float4*)g_ef_s)[i] = __ldg(((const float4*)ef) + e);
    }
}

// ---------------- pull gather: g_agg[n] = h[n] + sum relu(h[src]+ef@We+be) ----------------
// One warp per node; lanes split 2 halves x 16 feature-lanes.
__global__ __launch_bounds__(256) void gather_kernel(
    const float* __restrict__ h,
    const float* __restrict__ We,
    const float* __restrict__ be)
{
    __shared__ float sWe[4 * HIDDEN];
    __shared__ float sbe[HIDDEN];
    int tid = threadIdx.x;
    for (int i = tid; i < 4 * HIDDEN; i += blockDim.x) sWe[i] = We[i];
    if (tid < HIDDEN) sbe[tid] = be[tid];
    if (blockIdx.x == 0 && tid < HIDDEN) { g_sum[tid] = 0.0; g_sq[tid] = 0.0; }
    __syncthreads();

    const int n    = blockIdx.x * 8 + (tid >> 5);
    const int lane = tid & 31;
    const int half = lane >> 4;
    const int fl   = lane & 15;
    const int f0   = fl * 4;

    const int beg = g_off[n];
    const int end = g_off[n + 1];

    const float4* ef4 = (const float4*)g_ef_s;

    float4 acc = make_float4(0.f, 0.f, 0.f, 0.f);
    #pragma unroll 2
    for (int i = beg + half; i < end; i += 2) {
        int s = __ldg(g_src_s + i);                    // contiguous (broadcast over 16 lanes)
        float4 efv = __ldg(ef4 + i);                   // contiguous
        float4 hv = __ldg(((const float4*)(h + (size_t)s * HIDDEN)) + fl);  // gathered row
        float m0 = sbe[f0 + 0] + efv.x * sWe[0 * HIDDEN + f0 + 0] + efv.y * sWe[1 * HIDDEN + f0 + 0]
                               + efv.z * sWe[2 * HIDDEN + f0 + 0] + efv.w * sWe[3 * HIDDEN + f0 + 0];
        float m1 = sbe[f0 + 1] + efv.x * sWe[0 * HIDDEN + f0 + 1] + efv.y * sWe[1 * HIDDEN + f0 + 1]
                               + efv.z * sWe[2 * HIDDEN + f0 + 1] + efv.w * sWe[3 * HIDDEN + f0 + 1];
        float m2 = sbe[f0 + 2] + efv.x * sWe[0 * HIDDEN + f0 + 2] + efv.y * sWe[1 * HIDDEN + f0 + 2]
                               + efv.z * sWe[2 * HIDDEN + f0 + 2] + efv.w * sWe[3 * HIDDEN + f0 + 2];
        float m3 = sbe[f0 + 3] + efv.x * sWe[0 * HIDDEN + f0 + 3] + efv.y * sWe[1 * HIDDEN + f0 + 3]
                               + efv.z * sWe[2 * HIDDEN + f0 + 3] + efv.w * sWe[3 * HIDDEN + f0 + 3];
        acc.x += fmaxf(m0 + hv.x, 0.f);
        acc.y += fmaxf(m1 + hv.y, 0.f);
        acc.z += fmaxf(m2 + hv.z, 0.f);
        acc.w += fmaxf(m3 + hv.w, 0.f);
    }
    acc.x += __shfl_xor_sync(0xFFFFFFFFu, acc.x, 16);
    acc.y += __shfl_xor_sync(0xFFFFFFFFu, acc.y, 16);
    acc.z += __shfl_xor_sync(0xFFFFFFFFu, acc.z, 16);
    acc.w += __shfl_xor_sync(0xFFFFFFFFu, acc.w, 16);

    if (half == 0) {
        float4 hv = __ldg(((const float4*)(h + (size_t)n * HIDDEN)) + fl);
        acc.x += hv.x; acc.y += hv.y; acc.z += hv.z; acc.w += hv.w;
        *(((float4*)(g_agg + (size_t)n * HIDDEN)) + fl) = acc;
    }
}

// ---------------- MLP: z = relu(z_in@W1+b1)@W2+b2, plus per-feature stats ----------------
// 256 threads, 64 nodes/block, float4 on k-axis.
__global__ __launch_bounds__(256) void mlp_kernel(
    const float* __restrict__ W1, const float* __restrict__ b1,
    const float* __restrict__ W2, const float* __restrict__ b2)
{
    extern __shared__ float smem[];
    float* sW  = smem;                         // 64*64
    float* sIn = smem + HIDDEN * HIDDEN;       // 64*PITCH
    float* sT  = sIn + 64 * PITCH;             // 64*PITCH

    const int tid = threadIdx.x;
    const int tf = tid & 15;
    const int tn = tid >> 4;     // 0..15
    const int f0 = tf * 4;
    const int n0 = tn * 4;
    const int node0 = blockIdx.x * 64;

    for (int i = tid; i < HIDDEN * HIDDEN; i += 256) sW[i] = __ldg(W1 + i);
    for (int i = tid; i < 64 * HIDDEN / 4; i += 256) {
        int nn = i >> 4, c = i & 15;
        float4 v = (node0 + nn < N_NODES)
                 ? *(((const float4*)(g_agg + (size_t)(node0 + nn) * HIDDEN)) + c)
                 : make_float4(0.f, 0.f, 0.f, 0.f);
        *(float4*)(sIn + nn * PITCH + c * 4) = v;
    }
    __syncthreads();

    float acc[4][4];
    {
        float4 bias = __ldg(((const float4*)b1) + tf);
        #pragma unroll
        for (int i = 0; i < 4; i++) {
            acc[i][0] = bias.x; acc[i][1] = bias.y; acc[i][2] = bias.z; acc[i][3] = bias.w;
        }
    }
    #pragma unroll 4
    for (int kb = 0; kb < HIDDEN; kb += 4) {
        float4 w0 = *(const float4*)(sW + (kb + 0) * HIDDEN + f0);
        float4 w1 = *(const float4*)(sW + (kb + 1) * HIDDEN + f0);
        float4 w2 = *(const float4*)(sW + (kb + 2) * HIDDEN + f0);
        float4 w3 = *(const float4*)(sW + (kb + 3) * HIDDEN + f0);
        #pragma unroll
        for (int i = 0; i < 4; i++) {
            float4 a = *(const float4*)(sIn + (n0 + i) * PITCH + kb);
            acc[i][0] += a.x * w0.x + a.y * w1.x + a.z * w2.x + a.w * w3.x;
            acc[i][1] += a.x * w0.y + a.y * w1.y + a.z * w2.y + a.w * w3.y;
            acc[i][2] += a.x * w0.z + a.y * w1.z + a.z * w2.z + a.w * w3.z;
            acc[i][3] += a.x * w0.w + a.y * w1.w + a.z * w2.w + a.w * w3.w;
        }
    }
    #pragma unroll
    for (int i = 0; i < 4; i++) {
        float4 r = make_float4(fmaxf(acc[i][0], 0.f), fmaxf(acc[i][1], 0.f),
                               fmaxf(acc[i][2], 0.f), fmaxf(acc[i][3], 0.f));
        *(float4*)(sT + (n0 + i) * PITCH + f0) = r;
    }
    __syncthreads();

    for (int i = tid; i < HIDDEN * HIDDEN; i += 256) sW[i] = __ldg(W2 + i);
    __syncthreads();

    {
        float4 bias = __ldg(((const float4*)b2) + tf);
        #pragma unroll
        for (int i = 0; i < 4; i++) {
            acc[i][0] = bias.x; acc[i][1] = bias.y; acc[i][2] = bias.z; acc[i][3] = bias.w;
        }
    }
    #pragma unroll 4
    for (int kb = 0; kb < HIDDEN; kb += 4) {
        float4 w0 = *(const float4*)(sW + (kb + 0) * HIDDEN + f0);
        float4 w1 = *(const float4*)(sW + (kb + 1) * HIDDEN + f0);
        float4 w2 = *(const float4*)(sW + (kb + 2) * HIDDEN + f0);
        float4 w3 = *(const float4*)(sW + (kb + 3) * HIDDEN + f0);
        #pragma unroll
        for (int i = 0; i < 4; i++) {
            float4 a = *(const float4*)(sT + (n0 + i) * PITCH + kb);
            acc[i][0] += a.x * w0.x + a.y * w1.x + a.z * w2.x + a.w * w3.x;
            acc[i][1] += a.x * w0.y + a.y * w1.y + a.z * w2.y + a.w * w3.y;
            acc[i][2] += a.x * w0.z + a.y * w1.z + a.z * w2.z + a.w * w3.z;
            acc[i][3] += a.x * w0.w + a.y * w1.w + a.z * w2.w + a.w * w3.w;
        }
    }

    float ps[4], pq[4];
    #pragma unroll
    for (int j = 0; j < 4; j++) { ps[j] = 0.f; pq[j] = 0.f; }
    #pragma unroll
    for (int i = 0; i < 4; i++) {
        int node = node0 + n0 + i;
        if (node < N_NODES) {
            float4 v = make_float4(acc[i][0], acc[i][1], acc[i][2], acc[i][3]);
            *(((float4*)(g_z + (size_t)node * HIDDEN)) + tf) = v;
            #pragma unroll
            for (int j = 0; j < 4; j++) { ps[j] += acc[i][j]; pq[j] += acc[i][j] * acc[i][j]; }
        }
    }

    __syncthreads();
    float* rs = sIn;            // 1024 floats
    float* rq = sIn + 1024;     // 1024 floats
    #pragma unroll
    for (int j = 0; j < 4; j++) {
        rs[tn * HIDDEN + f0 + j] = ps[j];
        rq[tn * HIDDEN + f0 + j] = pq[j];
    }
    __syncthreads();
    if (tid < HIDDEN) {
        float s = 0.f, q = 0.f;
        #pragma unroll
        for (int g = 0; g < 16; g++) {
            s += rs[g * HIDDEN + tid];
            q += rq[g * HIDDEN + tid];
        }
        atomicAdd(&g_sum[tid], (double)s);
        atomicAdd(&g_sq[tid],  (double)q);
    }
}

// ---------------- BN + ReLU + residual: h = relu(scale*z + shift) + h ----------------
// scale/shift computed per block from g_sum/g_sq (replaces separate bnprep kernel).
__global__ __launch_bounds__(256) void bn_kernel(float* __restrict__ h,
                                                 const float* __restrict__ gamma,
                                                 const float* __restrict__ beta) {
    __shared__ float s_sc[HIDDEN], s_sh[HIDDEN];
    int t = threadIdx.x;
    if (t < HIDDEN) {
        double inv_n = 1.0 / (double)N_NODES;
        double mu  = g_sum[t] * inv_n;
        double var = g_sq[t] * inv_n - mu * mu;
        float rstd = rsqrtf((float)var + BN_EPS);
        float g = __ldg(gamma + t);
        s_sc[t] = g * rstd;
        s_sh[t] = __ldg(beta + t) - g * rstd * (float)mu;
    }
    __syncthreads();

    int i = blockIdx.x * blockDim.x + t;
    if (i >= N_NODES * HIDDEN / 4) return;
    int c = i & 15;
    float4 z  = ((const float4*)g_z)[i];
    float4 hv = ((float4*)h)[i];
    float4 sc = *(((const float4*)s_sc) + c);
    float4 sh = *(((const float4*)s_sh) + c);
    hv.x += fmaxf(z.x * sc.x + sh.x, 0.f);
    hv.y += fmaxf(z.y * sc.y + sh.y, 0.f);
    hv.z += fmaxf(z.z * sc.z + sh.z, 0.f);
    hv.w += fmaxf(z.w * sc.w + sh.w, 0.f);
    ((float4*)h)[i] = hv;
}

// ---------------- launch ----------------
extern "C" void kernel_launch(void* const* d_in, const int* in_sizes, int n_in,
                              void* d_out, int out_size) {
    const float* node_feat = (const float*)d_in[0];
    const float* edge_feat = (const float*)d_in[1];
    const int*   src       = (const int*)  d_in[2];
    const int*   dst       = (const int*)  d_in[3];
    const float* We        = (const float*)d_in[4];
    const float* be        = (const float*)d_in[5];
    const float* W1        = (const float*)d_in[6];
    const float* b1        = (const float*)d_in[7];
    const float* W2        = (const float*)d_in[8];
    const float* b2        = (const float*)d_in[9];
    const float* gamma     = (const float*)d_in[10];
    const float* beta      = (const float*)d_in[11];
    float* h = (float*)d_out;

    const int MLP_SMEM = (HIDDEN * HIDDEN + 2 * 64 * PITCH) * sizeof(float);  // 51200
    static bool attr_set = false;
    if (!attr_set) {
        cudaFuncSetAttribute(mlp_kernel, cudaFuncAttributeMaxDynamicSharedMemorySize, MLP_SMEM);
        attr_set = true;
    }

    const int ELEM4 = N_NODES * HIDDEN / 4;
    const int VEC_BLOCKS = (ELEM4 + 255) / 256;
    const int EDGE_BLOCKS = (N_EDGES + 255) / 256;

    copy_h_kernel<<<VEC_BLOCKS, 256>>>(node_feat, h);
    csr_hist_kernel<<<EDGE_BLOCKS, 256>>>(dst);
    csr_scan1_kernel<<<SCAN_NB, SCAN_B>>>();
    csr_scan2_kernel<<<1, 256>>>();
    csr_scan3_kernel<<<SCAN_NB, SCAN_B>>>();
    csr_place_kernel<<<EDGE_BLOCKS, 256>>>(dst);
    permute_kernel<<<EDGE_BLOCKS, 256>>>(src, edge_feat);

    for (int l = 0; l < N_LAYERS; l++) {
        gather_kernel<<<N_NODES / 8, 256>>>(h, We, be);
        mlp_kernel<<<(N_NODES + 63) / 64, 256, MLP_SMEM>>>(
            W1 + (size_t)l * HIDDEN * HIDDEN, b1 + (size_t)l * HIDDEN,
            W2 + (size_t)l * HIDDEN * HIDDEN, b2 + (size_t)l * HIDDEN);
        bn_kernel<<<VEC_BLOCKS, 256>>>(h,
                                       gamma + (size_t)l * HIDDEN,
                                       beta + (size_t)l * HIDDEN);
    }
}